// round 11
// baseline (speedup 1.0000x reference)
#include <cuda_runtime.h>
#include <cuda_fp16.h>
#include <math.h>
#include <stdint.h>

// ===========================================================================
// Problem constants
// ===========================================================================
#define B_ROWS 8192
#define P_ROWS 4096
#define D_DIM  512
#define NCHUNK (P_ROWS / 128)     // 32 column chunks of 128 protos

#define BM 128
#define BN 128
#define NTK (D_DIM / 16)           // 32 k16 tiles
#define NTP (P_ROWS / 16)          // 256 n16 (tile-pair) blocks
#define NMT (B_ROWS / 16)          // 512 m16 tiles

#define OFF_PSQ  0                 // 128 floats
#define OFF_PLAB 512               // 128 ints
#define OFF_C    1024
#define CPITCH 132                 // epilogue C smem pitch (floats)
#define EPI_BYTES (128 * CPITCH * 4)                     // 67584
#define SMEM_TOTAL (OFF_C + EPI_BYTES)                   // 68608 -> 2 CTAs/SM

// ===========================================================================
// Scratch (allocation-free)
// A in mma A-fragment order: [mt (512)][tk (32)][lane (32)] x uint4 (a0..a3)
// B in mma B-fragment order: [tk (32)][tp (256)][lane (32)] x uint4
//   uint4 = {tile 2tp: b0, b1, tile 2tp+1: b0, b1}
// ===========================================================================
__device__ uint4 g_Afrag[NMT * NTK * 32];
__device__ uint4 g_Bfrag[NTK * NTP * 32];
__device__ float g_fsq[B_ROWS];
__device__ float g_psq[P_ROWS];
__device__ float g_pmd[NCHUNK * B_ROWS];
__device__ float g_psd[NCHUNK * B_ROWS];
__device__ float g_pmn[NCHUNK * B_ROWS];
__device__ float g_psn[NCHUNK * B_ROWS];

#define MMA16816(c, a, b0, b1)                                                  \
    asm volatile("mma.sync.aligned.m16n8k16.row.col.f32.f16.f16.f32 "           \
        "{%0,%1,%2,%3}, {%4,%5,%6,%7}, {%8,%9}, {%0,%1,%2,%3};"                 \
        : "+f"((c)[0]), "+f"((c)[1]), "+f"((c)[2]), "+f"((c)[3])                \
        : "r"((a).x), "r"((a).y), "r"((a).z), "r"((a).w),                       \
          "r"(b0), "r"(b1))

// ===========================================================================
// Kernel 1: fp16 quantize + squared norms OF THE QUANTIZED vectors, writing
// both operands directly in mma.sync fragment order. One warp per row,
// float4 (16B) loads.
// ===========================================================================
__global__ void prep_kernel(const float* __restrict__ feat,
                            const float* __restrict__ proto) {
    int warp = (blockIdx.x * blockDim.x + threadIdx.x) >> 5;
    int lane = threadIdx.x & 31;
    if (warp >= B_ROWS + P_ROWS) return;
    bool isA = warp < B_ROWS;
    int row = isA ? warp : warp - B_ROWS;
    const float* src = (isA ? feat : proto) + (size_t)row * D_DIM;

    float s = 0.f;
    if (isA) {
        uint32_t* dst = (uint32_t*)g_Afrag;
        int mt = row >> 4;
        int tr = row & 15;
        int rsel = (tr >> 3) & 1;            // a0/a1 select
        int lane_base = (tr & 7) * 4;
#pragma unroll
        for (int t = 0; t < 4; t++) {
            int k = t * 128 + lane * 4;      // 4 consecutive floats
            float4 v = *(const float4*)(src + k);
            float x[4] = {v.x, v.y, v.z, v.w};
            uint32_t pk[2];
#pragma unroll
            for (int h = 0; h < 2; h++) {
                __half h0 = __float2half_rn(x[2 * h]);
                __half h1 = __float2half_rn(x[2 * h + 1]);
                float q0 = __half2float(h0), q1 = __half2float(h1);
                s = fmaf(q0, q0, fmaf(q1, q1, s));
                pk[h] = (uint32_t)__half_as_ushort(h0)
                      | ((uint32_t)__half_as_ushort(h1) << 16);
            }
            int tk = k >> 4;
            int kk = k & 15;
            int reg = rsel + ((kk >> 3) << 1);               // same for both pairs
            int lt0 = lane_base + ((kk & 7) >> 1);
            // pair 1 at kk+2: same reg, lane_t + 1
            dst[(uint32_t)(((mt * NTK + tk) * 32 + lt0) * 4 + reg)] = pk[0];
            dst[(uint32_t)(((mt * NTK + tk) * 32 + lt0 + 1) * 4 + reg)] = pk[1];
        }
    } else {
        uint32_t* dst = (uint32_t*)g_Bfrag;
        int pr = row & 7;            // n' within n8 tile
        int tp = row >> 4;           // tile-pair index
        int sub = (row >> 3) & 1;    // which tile of the pair
#pragma unroll
        for (int t = 0; t < 4; t++) {
            int k = t * 128 + lane * 4;
            float4 v = *(const float4*)(src + k);
            float x[4] = {v.x, v.y, v.z, v.w};
            uint32_t pk[2];
#pragma unroll
            for (int h = 0; h < 2; h++) {
                __half h0 = __float2half_rn(x[2 * h]);
                __half h1 = __float2half_rn(x[2 * h + 1]);
                float q0 = __half2float(h0), q1 = __half2float(h1);
                s = fmaf(q0, q0, fmaf(q1, q1, s));
                pk[h] = (uint32_t)__half_as_ushort(h0)
                      | ((uint32_t)__half_as_ushort(h1) << 16);
            }
#pragma unroll
            for (int h = 0; h < 2; h++) {
                int kk = k + 2 * h;
                uint32_t idx = (uint32_t)((((kk >> 4) * NTP + tp) * 32
                              + pr * 4 + ((kk & 7) >> 1)) * 4
                              + sub * 2 + ((kk >> 3) & 1));
                dst[idx] = pk[h];
            }
        }
    }
#pragma unroll
    for (int m = 16; m; m >>= 1) s += __shfl_xor_sync(0xffffffffu, s, m);
    if (lane == 0) {
        if (isA) g_fsq[row] = s; else g_psq[row] = s;
    }
}

// ===========================================================================
// Kernel 2: pure LDG->mma.sync mainloop, fragment-order operands, fully
// unrolled 32-tk loop. B prefetch distance 2 (ring-3), A distance 1 (ring-2).
// grid = (32 n-chunks, 64 m-tiles), 256 threads = 2(m) x 4(n) warps.
// ===========================================================================
__global__ __launch_bounds__(256, 2) void dce_mma_kernel(
    const int* __restrict__ label, const int* __restrict__ plab) {
    extern __shared__ __align__(1024) char smem[];
    float* psq_s = (float*)(smem + OFF_PSQ);
    int* plab_s = (int*)(smem + OFF_PLAB);

    const int tid = threadIdx.x;
    const int lane = tid & 31;
    const int wid = tid >> 5;
    const int wm = wid >> 2;       // 0..1
    const int wn = wid & 3;        // 0..3
    const int m0 = blockIdx.y * BM;
    const int n0 = blockIdx.x * BN;
    const int mt0 = (m0 >> 4) + wm * 4;    // first of this warp's 4 m16 tiles
    const int tp0 = (n0 >> 4) + wn * 2;    // first of this warp's 2 tile-pairs

    if (tid < 128) {
        psq_s[tid] = g_psq[n0 + tid];
        plab_s[tid] = plab[n0 + tid];
    }

    float acc[4][4][4];
#pragma unroll
    for (int i = 0; i < 4; i++)
#pragma unroll
        for (int j = 0; j < 4; j++)
#pragma unroll
            for (int q = 0; q < 4; q++) acc[i][j][q] = 0.f;

    const uint4* __restrict__ Af = g_Afrag;
    const uint4* __restrict__ Bf = g_Bfrag;

    uint4 a[2][4];      // A ring-2
    uint4 b[3][2];      // B ring-3 (prefetch distance 2)

    // preload: A tk0; B tk0, tk1
#pragma unroll
    for (int mt = 0; mt < 4; mt++)
        a[0][mt] = Af[((size_t)(mt0 + mt) * NTK + 0) * 32 + lane];
#pragma unroll
    for (int t = 0; t < 2; t++) {
        b[t][0] = Bf[((size_t)t * NTP + tp0) * 32 + lane];
        b[t][1] = Bf[((size_t)t * NTP + tp0 + 1) * 32 + lane];
    }

#pragma unroll
    for (int tk = 0; tk < NTK; tk++) {
        const int cur = tk % 2;          // A ring slot
        const int bc = tk % 3;           // B ring slot
        // B prefetch distance 2 (issue FIRST: longest latency)
        if (tk + 2 < NTK) {
            const int bn = (tk + 2) % 3;
            b[bn][0] = Bf[((size_t)(tk + 2) * NTP + tp0) * 32 + lane];
            b[bn][1] = Bf[((size_t)(tk + 2) * NTP + tp0 + 1) * 32 + lane];
        }
        // A prefetch distance 1 (mostly L1 hits: 4 warps share lines)
        if (tk + 1 < NTK) {
            const int an = (tk + 1) % 2;
#pragma unroll
            for (int mt = 0; mt < 4; mt++)
                a[an][mt] = Af[((size_t)(mt0 + mt) * NTK + tk + 1) * 32 + lane];
        }
#pragma unroll
        for (int mt = 0; mt < 4; mt++) {
            MMA16816(acc[mt][0], a[cur][mt], b[bc][0].x, b[bc][0].y);
            MMA16816(acc[mt][1], a[cur][mt], b[bc][0].z, b[bc][0].w);
            MMA16816(acc[mt][2], a[cur][mt], b[bc][1].x, b[bc][1].y);
            MMA16816(acc[mt][3], a[cur][mt], b[bc][1].z, b[bc][1].w);
        }
    }

    __syncthreads();   // psq_s/plab_s visible + everyone ready for C dump

    // --- dump accumulators to SMEM ---
    float* Cs = (float*)(smem + OFF_C);
#pragma unroll
    for (int mt = 0; mt < 4; mt++)
#pragma unroll
        for (int nt = 0; nt < 4; nt++) {
            int r = wm * 64 + mt * 16 + (lane >> 2);
            int c = wn * 32 + nt * 8 + ((lane & 3) << 1);
            Cs[r * CPITCH + c] = acc[mt][nt][0];
            Cs[r * CPITCH + c + 1] = acc[mt][nt][1];
            Cs[(r + 8) * CPITCH + c] = acc[mt][nt][2];
            Cs[(r + 8) * CPITCH + c + 1] = acc[mt][nt][3];
        }
    __syncthreads();

    // --- per-thread dual online LSE over 64 cols, pair-merge, write partials
    int row = tid >> 1;
    int c0 = (tid & 1) * 64;
    float fsq = g_fsq[m0 + row];
    int lab = label[m0 + row];
    float md = -INFINITY, mn = -INFINITY;
#pragma unroll 4
    for (int j = 0; j < 64; j++) {
        int col = c0 + j;
        float dot = Cs[row * CPITCH + col];
        float d2 = fmaxf(fsq + psq_s[col] - 2.0f * dot, 0.0f);
        float lg = -d2;
        Cs[row * CPITCH + col] = lg;
        md = fmaxf(md, lg);
        if (plab_s[col] == lab) mn = fmaxf(mn, lg);
    }
    float sd = 0.f, sn = 0.f;
#pragma unroll 4
    for (int j = 0; j < 64; j++) {
        int col = c0 + j;
        float lg = Cs[row * CPITCH + col];
        sd += __expf(lg - md);
        if (plab_s[col] == lab) sn += __expf(lg - mn);
    }
    // merge with partner thread (tid ^ 1, same warp)
    float md2 = __shfl_xor_sync(0xffffffffu, md, 1);
    float sd2 = __shfl_xor_sync(0xffffffffu, sd, 1);
    float mn2 = __shfl_xor_sync(0xffffffffu, mn, 1);
    float sn2 = __shfl_xor_sync(0xffffffffu, sn, 1);
    float M = fmaxf(md, md2);
    float SD = sd * __expf(md - M) + sd2 * __expf(md2 - M);
    float Mn = fmaxf(mn, mn2);
    float f0 = (mn == -INFINITY) ? 0.f : __expf(mn - Mn);
    float f1 = (mn2 == -INFINITY) ? 0.f : __expf(mn2 - Mn);
    float SN = sn * f0 + sn2 * f1;
    if ((tid & 1) == 0) {
        size_t o = (size_t)blockIdx.x * B_ROWS + m0 + row;
        g_pmd[o] = M;
        g_psd[o] = SD;
        g_pmn[o] = Mn;
        g_psn[o] = SN;
    }
}

// ===========================================================================
// Kernel 3: combine 32 chunk-partials per row -> loss.
// ===========================================================================
__global__ void combine_kernel(float* __restrict__ out) {
    int r = blockIdx.x * blockDim.x + threadIdx.x;
    if (r >= B_ROWS) return;
    float md = -INFINITY, sd = 0.f, mn = -INFINITY, sn = 0.f;
    for (int c = 0; c < NCHUNK; c++) {
        size_t o = (size_t)c * B_ROWS + r;
        float m2 = g_pmd[o], s2 = g_psd[o];
        float M = fmaxf(md, m2);
        sd = sd * __expf(md - M) + s2 * __expf(m2 - M);
        md = M;
        float mn2 = g_pmn[o], sn2 = g_psn[o];
        float Mn = fmaxf(mn, mn2);
        float f0 = (mn == -INFINITY) ? 0.f : __expf(mn - Mn);
        float f1 = (mn2 == -INFINITY) ? 0.f : __expf(mn2 - Mn);
        sn = sn * f0 + sn2 * f1;
        mn = Mn;
    }
    out[r] = (md + logf(sd)) - (mn + logf(sn));
}

// ===========================================================================
// Launch
// ===========================================================================
extern "C" void kernel_launch(void* const* d_in, const int* in_sizes, int n_in,
                              void* d_out, int out_size) {
    const float* feature = (const float*)d_in[0];
    const int* label = (const int*)d_in[1];
    const float* proto = (const float*)d_in[2];
    const int* plab = (const int*)d_in[3];
    float* out = (float*)d_out;

    cudaFuncSetAttribute(dce_mma_kernel, cudaFuncAttributeMaxDynamicSharedMemorySize,
                         SMEM_TOTAL);

    int warps = B_ROWS + P_ROWS;
    prep_kernel<<<(warps * 32 + 255) / 256, 256>>>(feature, proto);

    dim3 grid(P_ROWS / BN, B_ROWS / BM);
    dce_mma_kernel<<<grid, 256, SMEM_TOTAL>>>(label, plab);

    combine_kernel<<<(B_ROWS + 255) / 256, 256>>>(out);
}

// round 12
// speedup vs baseline: 1.0185x; 1.0185x over previous
#include <cuda_runtime.h>
#include <cuda_fp16.h>
#include <math.h>
#include <stdint.h>

// ===========================================================================
// Problem constants
// ===========================================================================
#define B_ROWS 8192
#define P_ROWS 4096
#define D_DIM  512
#define NCHUNK (P_ROWS / 128)     // 32 column chunks of 128 protos

#define BM 128
#define BN 128
#define NTK (D_DIM / 16)           // 32 k16 tiles
#define NTP (P_ROWS / 16)          // 256 n16 (tile-pair) blocks
#define NMT (B_ROWS / 16)          // 512 m16 tiles

#define OFF_PSQ  0                 // 128 floats
#define OFF_PLAB 512               // 128 ints
#define OFF_C    1024
#define CPITCH 132                 // epilogue C smem pitch (floats)
#define EPI_BYTES (128 * CPITCH * 4)                     // 67584
#define SMEM_TOTAL (OFF_C + EPI_BYTES)                   // 68608 -> 2 CTAs/SM

// ===========================================================================
// Scratch (allocation-free)
// A in mma A-fragment order: [mt (512)][tk (32)][lane (32)] x uint4 (a0..a3)
// B in mma B-fragment order: [tk (32)][tp (256)][lane (32)] x uint4
//   uint4 = {tile 2tp: b0, b1, tile 2tp+1: b0, b1}
// ===========================================================================
__device__ uint4 g_Afrag[NMT * NTK * 32];
__device__ uint4 g_Bfrag[NTK * NTP * 32];
__device__ float g_fsq[B_ROWS];
__device__ float g_psq[P_ROWS];
__device__ float g_pmd[NCHUNK * B_ROWS];
__device__ float g_psd[NCHUNK * B_ROWS];
__device__ float g_pmn[NCHUNK * B_ROWS];
__device__ float g_psn[NCHUNK * B_ROWS];

#define MMA16816(c, a, b0, b1)                                                  \
    asm volatile("mma.sync.aligned.m16n8k16.row.col.f32.f16.f16.f32 "           \
        "{%0,%1,%2,%3}, {%4,%5,%6,%7}, {%8,%9}, {%0,%1,%2,%3};"                 \
        : "+f"((c)[0]), "+f"((c)[1]), "+f"((c)[2]), "+f"((c)[3])                \
        : "r"((a).x), "r"((a).y), "r"((a).z), "r"((a).w),                       \
          "r"(b0), "r"(b1))

// ===========================================================================
// Kernel 1: staged prep. One 128-thread CTA per 16-row block (A: one mt,
// B: one tp). Coalesced float4 loads -> quantize -> smem fragment image ->
// coalesced uint4 stores. Norms of the QUANTIZED values via smem reduce.
// Fragment index formulas identical to the verified R10 scatter version.
// ===========================================================================
__global__ __launch_bounds__(128) void prep_kernel(
    const float* __restrict__ feat, const float* __restrict__ proto) {
    __shared__ uint32_t frag[4096];          // 16KB fragment image
    __shared__ float nrm[16][129];           // padded row partials

    const int t = threadIdx.x;
    const bool isA = blockIdx.x < NMT;
    const int grp = isA ? blockIdx.x : blockIdx.x - NMT;   // mt or tp
    const float* src = (isA ? feat : proto) + (size_t)grp * 16 * D_DIM;

    float np[16];
#pragma unroll
    for (int i = 0; i < 16; i++) np[i] = 0.f;

    // load + quantize + smem scatter: thread t owns float4 column t (k=4t..4t+3)
    const int k = t * 4;
#pragma unroll
    for (int i = 0; i < 16; i++) {
        float4 v = ((const float4*)src)[i * 128 + t];
        float x[4] = {v.x, v.y, v.z, v.w};
        uint32_t pk[2];
#pragma unroll
        for (int h = 0; h < 2; h++) {
            __half h0 = __float2half_rn(x[2 * h]);
            __half h1 = __float2half_rn(x[2 * h + 1]);
            float q0 = __half2float(h0), q1 = __half2float(h1);
            np[i] = fmaf(q0, q0, fmaf(q1, q1, np[i]));
            pk[h] = (uint32_t)__half_as_ushort(h0)
                  | ((uint32_t)__half_as_ushort(h1) << 16);
        }
        if (isA) {
            int tr = i;
            int rsel = tr >> 3;
            int lane_base = (tr & 7) * 4;
            int tk = k >> 4;
            int kk = k & 15;
            int reg = rsel + ((kk >> 3) << 1);
            int lt0 = lane_base + ((kk & 7) >> 1);
            frag[(tk * 32 + lt0) * 4 + reg] = pk[0];
            frag[(tk * 32 + lt0 + 1) * 4 + reg] = pk[1];
        } else {
            int pr = i & 7;
            int sub = (i >> 3) & 1;
#pragma unroll
            for (int h = 0; h < 2; h++) {
                int kk2 = k + 2 * h;
                int tk = kk2 >> 4;
                int kkl = kk2 & 15;
                frag[tk * 128 + (pr * 4 + ((kkl & 7) >> 1)) * 4
                     + sub * 2 + ((kkl >> 3) & 1)] = pk[h];
            }
        }
#pragma unroll
        for (int h = 0; h < 1; h++) {}       // (keep loop structure simple)
        nrm[i][t] = np[i];
    }
    __syncthreads();

    // norm reduce: 8 threads per row, each sums 16 entries, then shuffle
    {
        int row = t >> 3;
        int l8 = t & 7;
        float s = 0.f;
#pragma unroll
        for (int j = 0; j < 16; j++) s += nrm[row][l8 + 8 * j];
#pragma unroll
        for (int m = 4; m; m >>= 1) s += __shfl_xor_sync(0xffffffffu, s, m);
        if (l8 == 0) {
            if (isA) g_fsq[grp * 16 + row] = s;
            else     g_psq[grp * 16 + row] = s;
        }
    }
    __syncthreads();

    // coalesced fragment stores
    const uint4* fv = (const uint4*)frag;    // 1024 uint4
    if (isA) {
        uint4* dst = g_Afrag + (size_t)grp * NTK * 32;   // contiguous 16KB
#pragma unroll
        for (int j = 0; j < 8; j++) dst[j * 128 + t] = fv[j * 128 + t];
    } else {
#pragma unroll
        for (int pass = 0; pass < 8; pass++) {
            int tk = pass * 4 + (t >> 5);
            int w = t & 31;
            g_Bfrag[((size_t)tk * NTP + grp) * 32 + w] = fv[tk * 32 + w];
        }
    }
}

// ===========================================================================
// Kernel 2: pure LDG->mma.sync mainloop (fragment-order operands, L2-hot,
// register double-buffered). NO smem, NO syncs in mainloop. (R10 champion.)
// grid = (32 n-chunks, 64 m-tiles), 256 threads = 2(m) x 4(n) warps.
// ===========================================================================
__global__ __launch_bounds__(256, 2) void dce_mma_kernel(
    const int* __restrict__ label, const int* __restrict__ plab) {
    extern __shared__ __align__(1024) char smem[];
    float* psq_s = (float*)(smem + OFF_PSQ);
    int* plab_s = (int*)(smem + OFF_PLAB);

    const int tid = threadIdx.x;
    const int lane = tid & 31;
    const int wid = tid >> 5;
    const int wm = wid >> 2;       // 0..1
    const int wn = wid & 3;        // 0..3
    const int m0 = blockIdx.y * BM;
    const int n0 = blockIdx.x * BN;
    const int mt0 = (m0 >> 4) + wm * 4;    // first of this warp's 4 m16 tiles
    const int tp0 = (n0 >> 4) + wn * 2;    // first of this warp's 2 tile-pairs

    if (tid < 128) {
        psq_s[tid] = g_psq[n0 + tid];
        plab_s[tid] = plab[n0 + tid];
    }

    float acc[4][4][4];
#pragma unroll
    for (int i = 0; i < 4; i++)
#pragma unroll
        for (int j = 0; j < 4; j++)
#pragma unroll
            for (int q = 0; q < 4; q++) acc[i][j][q] = 0.f;

    const uint4* __restrict__ Af = g_Afrag;
    const uint4* __restrict__ Bf = g_Bfrag;

    uint4 a[2][4], b[2][2];
    // preload tk = 0
#pragma unroll
    for (int mt = 0; mt < 4; mt++)
        a[0][mt] = Af[((size_t)(mt0 + mt) * NTK + 0) * 32 + lane];
    b[0][0] = Bf[((size_t)0 * NTP + tp0) * 32 + lane];
    b[0][1] = Bf[((size_t)0 * NTP + tp0 + 1) * 32 + lane];

#pragma unroll 2
    for (int tk = 0; tk < NTK; tk++) {
        int cur = tk & 1, nxt = cur ^ 1;
        if (tk + 1 < NTK) {
#pragma unroll
            for (int mt = 0; mt < 4; mt++)
                a[nxt][mt] = Af[((size_t)(mt0 + mt) * NTK + tk + 1) * 32 + lane];
            b[nxt][0] = Bf[((size_t)(tk + 1) * NTP + tp0) * 32 + lane];
            b[nxt][1] = Bf[((size_t)(tk + 1) * NTP + tp0 + 1) * 32 + lane];
        }
#pragma unroll
        for (int mt = 0; mt < 4; mt++) {
            MMA16816(acc[mt][0], a[cur][mt], b[cur][0].x, b[cur][0].y);
            MMA16816(acc[mt][1], a[cur][mt], b[cur][0].z, b[cur][0].w);
            MMA16816(acc[mt][2], a[cur][mt], b[cur][1].x, b[cur][1].y);
            MMA16816(acc[mt][3], a[cur][mt], b[cur][1].z, b[cur][1].w);
        }
    }

    __syncthreads();   // psq_s/plab_s visible + everyone ready for C dump

    // --- dump accumulators to SMEM ---
    float* Cs = (float*)(smem + OFF_C);
#pragma unroll
    for (int mt = 0; mt < 4; mt++)
#pragma unroll
        for (int nt = 0; nt < 4; nt++) {
            int r = wm * 64 + mt * 16 + (lane >> 2);
            int c = wn * 32 + nt * 8 + ((lane & 3) << 1);
            Cs[r * CPITCH + c] = acc[mt][nt][0];
            Cs[r * CPITCH + c + 1] = acc[mt][nt][1];
            Cs[(r + 8) * CPITCH + c] = acc[mt][nt][2];
            Cs[(r + 8) * CPITCH + c + 1] = acc[mt][nt][3];
        }
    __syncthreads();

    // --- per-thread dual online LSE over 64 cols, pair-merge, write partials
    int row = tid >> 1;
    int c0 = (tid & 1) * 64;
    float fsq = g_fsq[m0 + row];
    int lab = label[m0 + row];
    float md = -INFINITY, mn = -INFINITY;
#pragma unroll 4
    for (int j = 0; j < 64; j++) {
        int col = c0 + j;
        float dot = Cs[row * CPITCH + col];
        float d2 = fmaxf(fsq + psq_s[col] - 2.0f * dot, 0.0f);
        float lg = -d2;
        Cs[row * CPITCH + col] = lg;
        md = fmaxf(md, lg);
        if (plab_s[col] == lab) mn = fmaxf(mn, lg);
    }
    float sd = 0.f, sn = 0.f;
#pragma unroll 4
    for (int j = 0; j < 64; j++) {
        int col = c0 + j;
        float lg = Cs[row * CPITCH + col];
        sd += __expf(lg - md);
        if (plab_s[col] == lab) sn += __expf(lg - mn);
    }
    // merge with partner thread (tid ^ 1, same warp)
    float md2 = __shfl_xor_sync(0xffffffffu, md, 1);
    float sd2 = __shfl_xor_sync(0xffffffffu, sd, 1);
    float mn2 = __shfl_xor_sync(0xffffffffu, mn, 1);
    float sn2 = __shfl_xor_sync(0xffffffffu, sn, 1);
    float M = fmaxf(md, md2);
    float SD = sd * __expf(md - M) + sd2 * __expf(md2 - M);
    float Mn = fmaxf(mn, mn2);
    float f0 = (mn == -INFINITY) ? 0.f : __expf(mn - Mn);
    float f1 = (mn2 == -INFINITY) ? 0.f : __expf(mn2 - Mn);
    float SN = sn * f0 + sn2 * f1;
    if ((tid & 1) == 0) {
        size_t o = (size_t)blockIdx.x * B_ROWS + m0 + row;
        g_pmd[o] = M;
        g_psd[o] = SD;
        g_pmn[o] = Mn;
        g_psn[o] = SN;
    }
}

// ===========================================================================
// Kernel 3: combine 32 chunk-partials per row -> loss. Two independent
// LSE chains (halved dependent-latency), merged at the end.
// ===========================================================================
__global__ void combine_kernel(float* __restrict__ out) {
    int r = blockIdx.x * blockDim.x + threadIdx.x;
    if (r >= B_ROWS) return;
    float md[2] = {-INFINITY, -INFINITY}, sd[2] = {0.f, 0.f};
    float mn[2] = {-INFINITY, -INFINITY}, sn[2] = {0.f, 0.f};
#pragma unroll
    for (int h = 0; h < 2; h++) {
        for (int c = h * 16; c < h * 16 + 16; c++) {
            size_t o = (size_t)c * B_ROWS + r;
            float m2 = g_pmd[o], s2 = g_psd[o];
            float M = fmaxf(md[h], m2);
            sd[h] = sd[h] * __expf(md[h] - M) + s2 * __expf(m2 - M);
            md[h] = M;
            float mm = g_pmn[o], ss = g_psn[o];
            float Mn = fmaxf(mn[h], mm);
            float f0 = (mn[h] == -INFINITY) ? 0.f : __expf(mn[h] - Mn);
            float f1 = (mm == -INFINITY) ? 0.f : __expf(mm - Mn);
            sn[h] = sn[h] * f0 + ss * f1;
            mn[h] = Mn;
        }
    }
    float M = fmaxf(md[0], md[1]);
    float SD = sd[0] * __expf(md[0] - M) + sd[1] * __expf(md[1] - M);
    float Mn = fmaxf(mn[0], mn[1]);
    float f0 = (mn[0] == -INFINITY) ? 0.f : __expf(mn[0] - Mn);
    float f1 = (mn[1] == -INFINITY) ? 0.f : __expf(mn[1] - Mn);
    float SN = sn[0] * f0 + sn[1] * f1;
    out[r] = (M + logf(SD)) - (Mn + logf(SN));
}

// ===========================================================================
// Launch
// ===========================================================================
extern "C" void kernel_launch(void* const* d_in, const int* in_sizes, int n_in,
                              void* d_out, int out_size) {
    const float* feature = (const float*)d_in[0];
    const int* label = (const int*)d_in[1];
    const float* proto = (const float*)d_in[2];
    const int* plab = (const int*)d_in[3];
    float* out = (float*)d_out;

    cudaFuncSetAttribute(dce_mma_kernel, cudaFuncAttributeMaxDynamicSharedMemorySize,
                         SMEM_TOTAL);

    prep_kernel<<<NMT + NTP, 128>>>(feature, proto);

    dim3 grid(P_ROWS / BN, B_ROWS / BM);
    dce_mma_kernel<<<grid, 256, SMEM_TOTAL>>>(label, plab);

    combine_kernel<<<(B_ROWS + 255) / 256, 256>>>(out);
}